// round 17
// baseline (speedup 1.0000x reference)
#include <cuda_runtime.h>
#include <cuda_bf16.h>
#include <cstdint>
#include <math.h>

// Problem constants
#define BB 2
#define TT 2048
#define CC 2048
#define HH 32
#define HKV 8
#define DD 64
#define MROWS (BB*TT)          // 4096
#define NQKV 3072              // H*D + 2*HKV*D

// Scratch (device globals: allocation-free per harness rules)
__device__ float g_qkv[MROWS * NQKV];          // [m][3072]  q|k|v
__device__ float g_q[BB * HH * TT * DD];       // [b][h][t][d]  (RoPE'd, tf32-rounded)
__device__ float g_k[BB * HKV * TT * DD];      // [b][hk][t][d] (RoPE'd, tf32-rounded)
__device__ float g_y[MROWS * CC];              // attention out (tf32-rounded)
__device__ float g_ct[TT * 32];                // cos table
__device__ float g_st[TT * 32];                // sin table

// ---------------------------------------------------------------------------
// helpers
// ---------------------------------------------------------------------------
__device__ __forceinline__ uint32_t f2tf(float f) {
    uint32_t r;
    asm("cvt.rna.tf32.f32 %0, %1;" : "=r"(r) : "f"(f));
    return r;
}

__device__ __forceinline__ void mma_tf32(float* c,
                                         uint32_t a0, uint32_t a1, uint32_t a2, uint32_t a3,
                                         uint32_t b0, uint32_t b1) {
    asm volatile(
        "mma.sync.aligned.m16n8k8.row.col.f32.tf32.tf32.f32 "
        "{%0,%1,%2,%3}, {%4,%5,%6,%7}, {%8,%9}, {%0,%1,%2,%3};"
        : "+f"(c[0]), "+f"(c[1]), "+f"(c[2]), "+f"(c[3])
        : "r"(a0), "r"(a1), "r"(a2), "r"(a3), "r"(b0), "r"(b1));
}

__device__ __forceinline__ uint32_t smem_u32(const void* p) {
    uint32_t a;
    asm("{ .reg .u64 t; cvta.to.shared.u64 t, %1; cvt.u32.u64 %0, t; }" : "=r"(a) : "l"(p));
    return a;
}

__device__ __forceinline__ void cp16(uint32_t d, const void* s) {
    asm volatile("cp.async.cg.shared.global [%0], [%1], 16;" :: "r"(d), "l"(s) : "memory");
}
__device__ __forceinline__ void cp_commit() {
    asm volatile("cp.async.commit_group;" ::: "memory");
}
template<int N> __device__ __forceinline__ void cp_wait() {
    asm volatile("cp.async.wait_group %0;" :: "n"(N) : "memory");
}

// ---------------------------------------------------------------------------
// tf32 tensor-core GEMM body — R6 structure (static 20 KB smem, single buffer,
// store -> sync -> prefetch -> mma -> sync), cvt.rna in the smem store path
// (measured free in R13). C[m][n] = sum_k A[m][k]*B[n][k]; K = 2048.
// ---------------------------------------------------------------------------
#define SROW 20

__device__ __forceinline__ void gemm_body(const float* __restrict__ A,
                                          const float* __restrict__ B,
                                          float* __restrict__ C,
                                          int ldc, int bm, int bn)
{
    __shared__ uint32_t As[128 * SROW];
    __shared__ uint32_t Bs[128 * SROW];

    const int tid = threadIdx.x;
    const int lane = tid & 31, w = tid >> 5;
    const int wm = w >> 1, wn = w & 1;     // warp grid 4x2
    const int g = lane >> 2, tg = lane & 3;
    const int lr = tid >> 1;               // 0..127
    const int lc = (tid & 1) * 8;          // 0 or 8

    const float* Ap = A + (size_t)(bm + lr) * 2048 + lc;
    const float* Bp = B + (size_t)(bn + lr) * 2048 + lc;

    float acc[16][4];
#pragma unroll
    for (int i = 0; i < 16; i++)
#pragma unroll
        for (int j = 0; j < 4; j++) acc[i][j] = 0.f;

    const int nt = 128;   // K / 16

    float4 ra0 = *(const float4*)(Ap);
    float4 ra1 = *(const float4*)(Ap + 4);
    float4 rb0 = *(const float4*)(Bp);
    float4 rb1 = *(const float4*)(Bp + 4);

    uint32_t* ap = &As[lr * SROW + lc];
    uint32_t* bp = &Bs[lr * SROW + lc];

    for (int kt = 0; kt < nt; kt++) {
        ap[0] = f2tf(ra0.x); ap[1] = f2tf(ra0.y); ap[2] = f2tf(ra0.z); ap[3] = f2tf(ra0.w);
        ap[4] = f2tf(ra1.x); ap[5] = f2tf(ra1.y); ap[6] = f2tf(ra1.z); ap[7] = f2tf(ra1.w);
        bp[0] = f2tf(rb0.x); bp[1] = f2tf(rb0.y); bp[2] = f2tf(rb0.z); bp[3] = f2tf(rb0.w);
        bp[4] = f2tf(rb1.x); bp[5] = f2tf(rb1.y); bp[6] = f2tf(rb1.z); bp[7] = f2tf(rb1.w);
        __syncthreads();

        if (kt + 1 < nt) {
            const float* An = Ap + (size_t)(kt + 1) * 16;
            const float* Bn = Bp + (size_t)(kt + 1) * 16;
            ra0 = *(const float4*)(An);
            ra1 = *(const float4*)(An + 4);
            rb0 = *(const float4*)(Bn);
            rb1 = *(const float4*)(Bn + 4);
        }

#pragma unroll
        for (int kk = 0; kk < 16; kk += 8) {
            uint32_t af[2][4], bf[8][2];
#pragma unroll
            for (int mi = 0; mi < 2; mi++) {
                int r = wm * 32 + mi * 16 + g;
                af[mi][0] = As[r * SROW + kk + tg];
                af[mi][1] = As[(r + 8) * SROW + kk + tg];
                af[mi][2] = As[r * SROW + kk + tg + 4];
                af[mi][3] = As[(r + 8) * SROW + kk + tg + 4];
            }
#pragma unroll
            for (int ni = 0; ni < 8; ni++) {
                int n = wn * 64 + ni * 8 + g;
                bf[ni][0] = Bs[n * SROW + kk + tg];
                bf[ni][1] = Bs[n * SROW + kk + tg + 4];
            }
#pragma unroll
            for (int mi = 0; mi < 2; mi++)
#pragma unroll
                for (int ni = 0; ni < 8; ni++)
                    mma_tf32(acc[mi * 8 + ni],
                             af[mi][0], af[mi][1], af[mi][2], af[mi][3],
                             bf[ni][0], bf[ni][1]);
        }
        __syncthreads();
    }

#pragma unroll
    for (int mi = 0; mi < 2; mi++) {
        int row = bm + wm * 32 + mi * 16 + g;
#pragma unroll
        for (int ni = 0; ni < 8; ni++) {
            int col = bn + wn * 64 + ni * 8 + tg * 2;
            const float* a = acc[mi * 8 + ni];
            *(float2*)&C[(size_t)row * ldc + col]       = make_float2(a[0], a[1]);
            *(float2*)&C[(size_t)(row + 8) * ldc + col] = make_float2(a[2], a[3]);
        }
    }
}

// Fused QKV projection: one launch covers Wq (16 n-tiles), Wk (4), Wv (4).
__global__ __launch_bounds__(256)
void qkv_gemm(const float* __restrict__ x, const float* __restrict__ Wq,
              const float* __restrict__ Wk, const float* __restrict__ Wv,
              float* __restrict__ qkv)
{
    int nx = blockIdx.x;
    const float* B;
    int bn, coff;
    if (nx < 16)      { B = Wq; bn = nx * 128;        coff = 0; }
    else if (nx < 20) { B = Wk; bn = (nx - 16) * 128; coff = 2048; }
    else              { B = Wv; bn = (nx - 20) * 128; coff = 2560; }
    gemm_body(x, B, qkv + coff, NQKV, blockIdx.y * 128, bn);
}

// Output projection: out = y @ Wc^T
__global__ __launch_bounds__(256)
void proj_gemm(const float* __restrict__ y, const float* __restrict__ Wc,
               float* __restrict__ out)
{
    gemm_body(y, Wc, out, CC, blockIdx.y * 128, blockIdx.x * 128);
}

// ---------------------------------------------------------------------------
// RoPE cos/sin table (double precision)
// ---------------------------------------------------------------------------
__global__ void rope_tab(const int* __restrict__ pos,
                         float* __restrict__ ct, float* __restrict__ st)
{
    int idx = blockIdx.x * blockDim.x + threadIdx.x;
    if (idx >= TT * 32) return;
    int t = idx >> 5, j = idx & 31;
    double ang = (double)pos[t] * pow(10000.0, -(double)j / 32.0);
    double s, c;
    sincos(ang, &s, &c);
    ct[idx] = (float)c;
    st[idx] = (float)s;
}

// ---------------------------------------------------------------------------
// RoPE + reshape (+ fused in-place tf32 rounding of the V region).
// Work units per (b,t): heads 0..39 = RoPE pairs; units 40..43 = V rounding
// (each handles 32 float4s of the 128-float4 V row).
// ---------------------------------------------------------------------------
__global__ void rope_reshape(float* __restrict__ qkv,
                             const float* __restrict__ ct, const float* __restrict__ st,
                             float* __restrict__ Qr, float* __restrict__ Kr)
{
    const int PPT = 44 * 32;   // 40 rope-head units + 4 V-round units
    int idx = blockIdx.x * blockDim.x + threadIdx.x;
    if (idx >= BB * TT * PPT) return;
    int m = idx / PPT;
    int r = idx - m * PPT;
    int head = r >> 5, dp = r & 31;
    int b = m / TT, t = m - b * TT;

    float* row = qkv + (size_t)m * NQKV;

    if (head >= 40) {
        // tf32-round V in place: element group (head-40)*32 + dp of 128 float4s
        int c4 = (head - 40) * 32 + dp;
        float4* p = (float4*)(row + 2560) + c4;
        float4 v = *p;
        v.x = __uint_as_float(f2tf(v.x));
        v.y = __uint_as_float(f2tf(v.y));
        v.z = __uint_as_float(f2tf(v.z));
        v.w = __uint_as_float(f2tf(v.w));
        *p = v;
        return;
    }

    float x0, x1;
    float* dst;
    if (head < HH) {
        x0 = row[head * 64 + dp];
        x1 = row[head * 64 + dp + 32];
        dst = Qr + ((size_t)(b * HH + head) * TT + t) * 64;
    } else {
        int hk = head - HH;
        x0 = row[2048 + hk * 64 + dp];
        x1 = row[2048 + hk * 64 + dp + 32];
        dst = Kr + ((size_t)(b * HKV + hk) * TT + t) * 64;
    }
    int j = dp >> 1;
    float c1 = ct[t * 32 + j],      s1 = st[t * 32 + j];
    float c2 = ct[t * 32 + j + 16], s2 = st[t * 32 + j + 16];
    dst[dp]      = __uint_as_float(f2tf(x0 * c1 - x1 * s1));
    dst[dp + 32] = __uint_as_float(f2tf(x1 * c2 + x0 * s2));
}

// ---------------------------------------------------------------------------
// Tensor-core flash attention (tf32 mma, fp32 softmax in registers).
//  - Q fragments hoisted to registers (staged once through smem, region then
//    reused for Ps).
//  - K/V double-buffered in smem, cp.async issued one compute iteration ahead.
//  - Conflict-free layouts (Ks/Ps stride 68, Vs stride 72, P stores 64-bit).
// ---------------------------------------------------------------------------
#define FS 68
#define VS 72
#define FLASH_SMEM ((128 * FS + 2 * 64 * FS + 2 * 64 * VS) * 4)

__global__ __launch_bounds__(256, 2)
void flash_attn_tc(const float* __restrict__ Q, const float* __restrict__ K,
                   const float* __restrict__ Vg, float* __restrict__ Y)
{
    extern __shared__ uint32_t smu[];
    uint32_t* Ps = smu;                    // [128][FS]; Q staging in prologue
    uint32_t* Ks = smu + 128 * FS;         // [2][64][FS]
    uint32_t* Vs = Ks + 2 * 64 * FS;       // [2][64][VS]

    const int tid = threadIdx.x;
    const int lane = tid & 31, w = tid >> 5;
    const int g = lane >> 2, tg = lane & 3;
    const int qt = (gridDim.x - 1) - blockIdx.x;   // heavy blocks first
    const int h = blockIdx.y, b = blockIdx.z, hk = h >> 2;
    const int qbase = qt * 128;
    const float scale = 0.125f;
    const int nkv = 2 * qt + 2;

    const int pr = tid >> 2, pc = (tid & 3) * 16;
    const float* Kg0 = K + (((size_t)(b * HKV + hk) * TT) + pr) * 64 + pc;
    const float* Vg0 = Vg + ((size_t)(b * TT + pr)) * NQKV + hk * 64 + pc;

    {
        uint32_t kd = smem_u32(Ks + pr * FS + pc);
        uint32_t vd = smem_u32(Vs + pr * VS + pc);
#pragma unroll
        for (int i = 0; i < 4; i++) {
            cp16(kd + i * 16, Kg0 + i * 4);
            cp16(vd + i * 16, Vg0 + i * 4);
        }
        cp_commit();
    }

    {
        int r = tid >> 1, c0 = (tid & 1) * 32;
        const uint4* src = (const uint4*)(Q + (((size_t)(b * HH + h) * TT) + qbase + r) * 64 + c0);
        uint4* dst = (uint4*)(Ps + r * FS + c0);
#pragma unroll
        for (int i = 0; i < 8; i++) dst[i] = src[i];
    }
    __syncthreads();

    const int slab = w * 16;
    uint32_t qf[8][4];
#pragma unroll
    for (int k8 = 0; k8 < 8; k8++) {
        int kk = k8 * 8;
        qf[k8][0] = Ps[(slab + g) * FS + kk + tg];
        qf[k8][1] = Ps[(slab + g + 8) * FS + kk + tg];
        qf[k8][2] = Ps[(slab + g) * FS + kk + tg + 4];
        qf[k8][3] = Ps[(slab + g + 8) * FS + kk + tg + 4];
    }
    __syncthreads();

    float Oc[8][4];
#pragma unroll
    for (int i = 0; i < 8; i++)
#pragma unroll
        for (int j = 0; j < 4; j++) Oc[i][j] = 0.f;

    float mrun0 = -1e30f, mrun1 = -1e30f, lrun0 = 0.f, lrun1 = 0.f;
    const int row0 = qbase + slab + g;
    const int row1 = row0 + 8;

    for (int jt = 0; jt < nkv; jt++) {
        cp_wait<0>();
        __syncthreads();

        if (jt + 1 < nkv) {
            int kb = (jt + 1) * 64;
            int s = (jt + 1) & 1;
            uint32_t kd = smem_u32(Ks + s * 64 * FS + pr * FS + pc);
            uint32_t vd = smem_u32(Vs + s * 64 * VS + pr * VS + pc);
            const float* kg = Kg0 + (size_t)kb * 64;
            const float* vg = Vg0 + (size_t)kb * NQKV;
#pragma unroll
            for (int i = 0; i < 4; i++) {
                cp16(kd + i * 16, kg + i * 4);
                cp16(vd + i * 16, vg + i * 4);
            }
            cp_commit();
        }

        const int kbase = jt * 64;
        const uint32_t* Kb = Ks + (jt & 1) * 64 * FS;
        const uint32_t* Vb = Vs + (jt & 1) * 64 * VS;

        float Sc[8][4];
#pragma unroll
        for (int i = 0; i < 8; i++)
#pragma unroll
            for (int j = 0; j < 4; j++) Sc[i][j] = 0.f;
#pragma unroll
        for (int k8 = 0; k8 < 8; k8++) {
            int kk = k8 * 8;
#pragma unroll
            for (int ni = 0; ni < 8; ni++) {
                uint32_t b0 = Kb[(ni * 8 + g) * FS + kk + tg];
                uint32_t b1 = Kb[(ni * 8 + g) * FS + kk + tg + 4];
                mma_tf32(Sc[ni], qf[k8][0], qf[k8][1], qf[k8][2], qf[k8][3], b0, b1);
            }
        }

        const bool needmask = (kbase + 63) > (qbase + slab);
        float mx0 = -1e30f, mx1 = -1e30f;
#pragma unroll
        for (int ni = 0; ni < 8; ni++) {
            int c = kbase + ni * 8 + 2 * tg;
            float s0 = Sc[ni][0] * scale, s1 = Sc[ni][1] * scale;
            float s2 = Sc[ni][2] * scale, s3 = Sc[ni][3] * scale;
            if (needmask) {
                if (c     > row0) s0 = -1e30f;
                if (c + 1 > row0) s1 = -1e30f;
                if (c     > row1) s2 = -1e30f;
                if (c + 1 > row1) s3 = -1e30f;
            }
            Sc[ni][0] = s0; Sc[ni][1] = s1; Sc[ni][2] = s2; Sc[ni][3] = s3;
            mx0 = fmaxf(mx0, fmaxf(s0, s1));
            mx1 = fmaxf(mx1, fmaxf(s2, s3));
        }
        mx0 = fmaxf(mx0, __shfl_xor_sync(0xffffffffu, mx0, 1));
        mx0 = fmaxf(mx0, __shfl_xor_sync(0xffffffffu, mx0, 2));
        mx1 = fmaxf(mx1, __shfl_xor_sync(0xffffffffu, mx1, 1));
        mx1 = fmaxf(mx1, __shfl_xor_sync(0xffffffffu, mx1, 2));

        float nm0 = fmaxf(mrun0, mx0), nm1 = fmaxf(mrun1, mx1);
        float ps0 = 0.f, ps1 = 0.f;
#pragma unroll
        for (int ni = 0; ni < 8; ni++) {
            float p0 = __expf(Sc[ni][0] - nm0);
            float p1 = __expf(Sc[ni][1] - nm0);
            float p2 = __expf(Sc[ni][2] - nm1);
            float p3 = __expf(Sc[ni][3] - nm1);
            ps0 += p0 + p1; ps1 += p2 + p3;
            uint2 w0; w0.x = f2tf(p0); w0.y = f2tf(p1);
            uint2 w1; w1.x = f2tf(p2); w1.y = f2tf(p3);
            *(uint2*)&Ps[(slab + g) * FS + ni * 8 + 2 * tg]     = w0;
            *(uint2*)&Ps[(slab + g + 8) * FS + ni * 8 + 2 * tg] = w1;
        }
        ps0 += __shfl_xor_sync(0xffffffffu, ps0, 1);
        ps0 += __shfl_xor_sync(0xffffffffu, ps0, 2);
        ps1 += __shfl_xor_sync(0xffffffffu, ps1, 1);
        ps1 += __shfl_xor_sync(0xffffffffu, ps1, 2);

        float rf0 = __expf(mrun0 - nm0), rf1 = __expf(mrun1 - nm1);
        lrun0 = lrun0 * rf0 + ps0;  lrun1 = lrun1 * rf1 + ps1;
        mrun0 = nm0;  mrun1 = nm1;
#pragma unroll
        for (int ni = 0; ni < 8; ni++) {
            Oc[ni][0] *= rf0; Oc[ni][1] *= rf0;
            Oc[ni][2] *= rf1; Oc[ni][3] *= rf1;
        }
        __syncwarp();

#pragma unroll
        for (int kk = 0; kk < 64; kk += 8) {
            uint32_t a0 = Ps[(slab + g) * FS + kk + tg];
            uint32_t a1 = Ps[(slab + g + 8) * FS + kk + tg];
            uint32_t a2 = Ps[(slab + g) * FS + kk + tg + 4];
            uint32_t a3 = Ps[(slab + g + 8) * FS + kk + tg + 4];
#pragma unroll
            for (int ni = 0; ni < 8; ni++) {
                uint32_t b0 = Vb[(kk + tg) * VS + ni * 8 + g];
                uint32_t b1 = Vb[(kk + tg + 4) * VS + ni * 8 + g];
                mma_tf32(Oc[ni], a0, a1, a2, a3, b0, b1);
            }
        }
    }

    float inv0 = 1.0f / lrun0, inv1 = 1.0f / lrun1;
#pragma unroll
    for (int ni = 0; ni < 8; ni++) {
        int col = h * 64 + ni * 8 + 2 * tg;
        *(float2*)&Y[((size_t)(b * TT) + row0) * CC + col] =
            make_float2(__uint_as_float(f2tf(Oc[ni][0] * inv0)),
                        __uint_as_float(f2tf(Oc[ni][1] * inv0)));
        *(float2*)&Y[((size_t)(b * TT) + row1) * CC + col] =
            make_float2(__uint_as_float(f2tf(Oc[ni][2] * inv1)),
                        __uint_as_float(f2tf(Oc[ni][3] * inv1)));
    }
}

// ---------------------------------------------------------------------------
extern "C" void kernel_launch(void* const* d_in, const int* in_sizes, int n_in,
                              void* d_out, int out_size)
{
    const float* x  = (const float*)d_in[0];
    const float* Wq = (const float*)d_in[1];
    const float* Wk = (const float*)d_in[2];
    const float* Wv = (const float*)d_in[3];
    const float* Wc = (const float*)d_in[4];
    const int* pos  = (const int*)d_in[5];
    float* out = (float*)d_out;

    float *qkv, *q, *k, *y, *ct, *st;
    cudaGetSymbolAddress((void**)&qkv, g_qkv);
    cudaGetSymbolAddress((void**)&q,   g_q);
    cudaGetSymbolAddress((void**)&k,   g_k);
    cudaGetSymbolAddress((void**)&y,   g_y);
    cudaGetSymbolAddress((void**)&ct,  g_ct);
    cudaGetSymbolAddress((void**)&st,  g_st);

    cudaFuncSetAttribute(flash_attn_tc, cudaFuncAttributeMaxDynamicSharedMemorySize, FLASH_SMEM);

    // RoPE table (independent of the GEMM; launch first)
    rope_tab<<<(TT * 32 + 255) / 256, 256>>>(pos, ct, st);

    // Fused QKV projection (cvt in store path; raw inputs)
    qkv_gemm<<<dim3(24, 32), 256>>>(x, Wq, Wk, Wv, qkv);

    // RoPE + reshape + fused V rounding
    rope_reshape<<<(BB * TT * 44 * 32 + 255) / 256, 256>>>(qkv, ct, st, q, k);

    // Flash attention (tf32 mma.sync, Q in regs, cp.async double-buffered KV)
    flash_attn_tc<<<dim3(TT / 128, HH, BB), 256, FLASH_SMEM>>>(q, k, qkv + 2560, y);

    // Output projection (cvt in store path)
    proj_gemm<<<dim3(16, 32), 256>>>(y, Wc, out);
}